// round 11
// baseline (speedup 1.0000x reference)
#include <cuda_runtime.h>
#include <cuda_fp16.h>
#include <cstdint>

// ================= problem constants =================
#define NB   1024
#define IIC  128
#define MGLOB (NB*784)            // 802816 flattened output rows
#define GRID_MAIN 304
#define THREADS 256
#define UNITS (MGLOB/32*2)        // 50176 warp units: (32m block) x (64i half)
#define TOTAL_WARPS (GRID_MAIN*(THREADS/32))

// ================= scratch =================
// g_R[(n*28+h')][idx 0..31][l 0..31]  fp16, 64B rows
__device__ __half g_R[(size_t)NB*28*32*32];   // 58.7 MB
__device__ int g_next;            // per-warp work-stealing counter
__device__ int g_done;            // reset coordinator

// ================= smem layout =================
#define WS_B32   (18*8*32*4)                    // 18432 b32 = 73728 B
#define SM_TOTAL (WS_B32*4)                     // weights only

__device__ __forceinline__ void mma_f16(float4& d, const uint4& a, uint32_t b0, uint32_t b1) {
    asm volatile(
        "mma.sync.aligned.m16n8k16.row.col.f32.f16.f16.f32 "
        "{%0,%1,%2,%3}, {%4,%5,%6,%7}, {%8,%9}, {%0,%1,%2,%3};"
        : "+f"(d.x), "+f"(d.y), "+f"(d.z), "+f"(d.w)
        : "r"(a.x), "r"(a.y), "r"(a.z), "r"(a.w), "r"(b0), "r"(b1));
}

// ================= prep kernel (unchanged, validated R9/R10) =================
__global__ __launch_bounds__(128) void prep_kernel(const float* __restrict__ x) {
    __shared__ float xs[64 * 29];
    const int p = blockIdx.x;            // n*28 + h'
    const int n = p / 28, h = p - n * 28;
    const int tid = threadIdx.x;

    const float4* x4 = reinterpret_cast<const float4*>(x);
    #pragma unroll 4
    for (int e = tid; e < 448; e += 128) {
        const int c = e / 7, f = e - c * 7;
        const float4 v = x4[((size_t)(n * 64 + c) * 28 + h) * 7 + f];
        float* dst = &xs[c * 29 + f * 4];
        dst[0] = v.x; dst[1] = v.y; dst[2] = v.z; dst[3] = v.w;
    }
    __syncthreads();

    __half* Rout = g_R + (size_t)p * 1024;
    const int l = tid & 31;
    const int q0 = tid >> 5;
    #pragma unroll
    for (int qq = 0; qq < 8; ++qq) {
        const int q = qq * 4 + q0;
        float v;
        if (q < 28) {
            int u1 = q - 1; if (u1 < 0) u1 += 28;
            int u2 = q - 2; if (u2 < 0) u2 += 28;
            v = xs[l * 29 + u1] + xs[(32 + l) * 29 + u2];
        } else if (q == 28) v = xs[(32 + l) * 29 + 25];   // k=0, w=0
        else if (q == 29)   v = xs[l * 29 + 27];          // k=0, w=1
        else if (q == 30)   v = xs[l * 29 + 0];           // k=2, w=0
        else                v = xs[(32 + l) * 29 + 26];   // k=2, w=27
        Rout[q * 32 + l] = __float2half_rn(v);
    }
}

// ================= main kernel =================
__global__ __launch_bounds__(THREADS, 2) void main_kernel(const float* __restrict__ Wg,
                                                          float* __restrict__ out) {
    extern __shared__ char smem[];
    uint32_t* wsb = reinterpret_cast<uint32_t*>(smem);
    const uint4* ws4 = reinterpret_cast<const uint4*>(smem);

    const int tid  = threadIdx.x;
    const int lane = tid & 31;
    const int gq   = lane >> 2;     // fragment groupID
    const int tig  = lane & 3;      // thread-in-group

    // ---- weights -> fp16 fragment-ready smem, once per CTA (validated R9/R10) ----
    for (int t = tid; t < WS_B32; t += THREADS) {
        const int reg = t & 3;
        const int ln  = (t >> 2) & 31;
        const int mt  = (t >> 7) & 7;
        const int S   = t >> 10;                  // 0..17
        const int r   = (ln >> 2) + ((reg & 1) << 3);
        const int k16 = ((ln & 3) << 1) + ((reg >> 1) << 3);
        const int i   = (mt << 4) + r;
        const int kp  = (S << 4) + k16;           // even
        const int c   = kp >> 5, l = kp & 31;
        const float w0 = Wg[(l * 9 + c) * 128 + i];
        const float w1 = Wg[((l + 1) * 9 + c) * 128 + i];
        const __half2 hv = __floats2half2_rn(w0, w1);
        wsb[t] = *reinterpret_cast<const uint32_t*>(&hv);
    }
    __syncthreads();   // the only CTA-wide barrier

    // ---- fully independent per-warp work-stealing loop ----
    while (true) {
        int u;
        if (lane == 0) u = atomicAdd(&g_next, 1);
        u = __shfl_sync(0xFFFFFFFFu, u, 0);
        if (u >= UNITS) break;

        const int ihalf = u & 1;
        const int mbase = (u >> 1) << 5;          // 32-m block

        // per-thread metadata for its 4 B-rows: m = mbase + nt*8 + gq
        int hq[4], baseq[4], ikx[4];              // ikx packs 3 x (ik<<5) in 10-bit fields
        #pragma unroll
        for (int nt = 0; nt < 4; ++nt) {
            const int m  = mbase + nt * 8 + gq;
            const int n  = m / 784;
            const int r  = m - n * 784;
            const int h  = r / 28;
            const int wp = r - h * 28;
            hq[nt]    = h;
            baseq[nt] = (n * 28 + h) << 10;       // halves
            const int ik0 = (wp == 0) ? 28 : (wp == 1) ? 29 : (wp - 1);
            const int ik2 = (wp == 0) ? 30 : (wp == 27) ? 31 : (wp + 1);
            ikx[nt] = (ik0 << 5) | (wp << 15) | (ik2 << 25);
        }

        // B loader: 8 uint32 (nt x reg) for chunk cc, half s
        #define LDB(dst, cc, ss) do {                                               \
            const int jj = ((cc) * 11) >> 5;                                        \
            const int kk = (cc) - jj * 3;                                           \
            _Pragma("unroll")                                                       \
            for (int nt = 0; nt < 4; ++nt) {                                        \
                uint32_t v0 = 0u, v1 = 0u;                                          \
                if ((unsigned)(hq[nt] + jj - 1) < 28u) {                            \
                    const int ik32 = (ikx[nt] >> (kk * 10)) & 1023;                 \
                    const uint32_t* p = reinterpret_cast<const uint32_t*>(          \
                        g_R + baseq[nt] + ((jj - 1) << 10) + ik32                   \
                            + ((ss) << 4) + (tig << 1));                            \
                    v0 = p[0];                                                      \
                    v1 = p[4];   /* +8 halves = reg 1 */                            \
                }                                                                   \
                dst[nt * 2 + 0] = v0;                                               \
                dst[nt * 2 + 1] = v1;                                               \
            } } while (0)

        float4 acc[4][4];
        #pragma unroll
        for (int a = 0; a < 4; ++a)
            #pragma unroll
            for (int b = 0; b < 4; ++b)
                acc[a][b] = make_float4(0.f, 0.f, 0.f, 0.f);

        uint32_t b_s0[2][8];      // double-buffered s=0 fragments
        uint32_t b_s1[8];         // s=1 fragments (loaded early in chunk)
        LDB(b_s0[0], 0, 0);

        // chunks: LDG s1(c) -> MMA s0(c) -> LDG s0(c+1) -> MMA s1(c)
        #pragma unroll
        for (int c = 0; c < 9; ++c) {
            LDB(b_s1, c, 1);

            {   // MMA s=0
                const int S = c * 2;
                uint4 afr[4];
                #pragma unroll
                for (int mtl = 0; mtl < 4; ++mtl)
                    afr[mtl] = ws4[((S << 3) + ihalf * 4 + mtl) * 32 + lane];
                #pragma unroll
                for (int mtl = 0; mtl < 4; ++mtl)
                    #pragma unroll
                    for (int ntl = 0; ntl < 4; ++ntl)
                        mma_f16(acc[mtl][ntl], afr[mtl],
                                b_s0[c & 1][ntl * 2], b_s0[c & 1][ntl * 2 + 1]);
            }

            if (c < 8) LDB(b_s0[(c + 1) & 1], c + 1, 0);

            {   // MMA s=1
                const int S = c * 2 + 1;
                uint4 afr[4];
                #pragma unroll
                for (int mtl = 0; mtl < 4; ++mtl)
                    afr[mtl] = ws4[((S << 3) + ihalf * 4 + mtl) * 32 + lane];
                #pragma unroll
                for (int mtl = 0; mtl < 4; ++mtl)
                    #pragma unroll
                    for (int ntl = 0; ntl < 4; ++ntl)
                        mma_f16(acc[mtl][ntl], afr[mtl],
                                b_s1[ntl * 2], b_s1[ntl * 2 + 1]);
            }
        }
        #undef LDB

        // ---- epilogue: coalesced float2 stores ----
        #pragma unroll
        for (int mtl = 0; mtl < 4; ++mtl) {
            const int i0 = ihalf * 64 + mtl * 16 + gq;
            #pragma unroll
            for (int ntl = 0; ntl < 4; ++ntl) {
                const int mgo = mbase + ntl * 8 + (tig << 1);
                const int n = mgo / 784;
                const int r = mgo - n * 784;     // float2 never straddles n (mgo even)
                const float4 v = acc[mtl][ntl];
                float* ob = out + (size_t)n * (IIC * 784) + r;
                *reinterpret_cast<float2*>(ob + (size_t)i0 * 784)       = make_float2(v.x, v.y);
                *reinterpret_cast<float2*>(ob + (size_t)(i0 + 8) * 784) = make_float2(v.z, v.w);
            }
        }
    }

    // ---- self-reset of work counters (deterministic, graph-replay safe) ----
    if (lane == 0) {
        const int old = atomicAdd(&g_done, 1);
        if (old == TOTAL_WARPS - 1) {   // every warp has finished
            g_next = 0;
            __threadfence();
            g_done = 0;
        }
    }
}

// ================= launch =================
extern "C" void kernel_launch(void* const* d_in, const int* in_sizes, int n_in,
                              void* d_out, int out_size) {
    const float* x  = (const float*)d_in[0];   // (1024,64,28,28)
    const float* Wg = (const float*)d_in[1];   // (32,3,3,128)
    float* out = (float*)d_out;                // (1024,128,28,28)

    prep_kernel<<<NB * 28, 128>>>(x);

    cudaFuncSetAttribute(main_kernel, cudaFuncAttributeMaxDynamicSharedMemorySize, SM_TOTAL);
    main_kernel<<<GRID_MAIN, THREADS, SM_TOTAL>>>(Wg, out);
}

// round 12
// speedup vs baseline: 1.1139x; 1.1139x over previous
#include <cuda_runtime.h>
#include <cuda_fp16.h>
#include <cstdint>

// ================= problem constants =================
#define NB   1024
#define IIC  128
#define MGLOB (NB*784)            // 802816 flattened output rows
#define GRID_MAIN 304
#define THREADS 256
#define UNITS (MGLOB/32)          // 25088 pair units of 32m x 128i
#define TOTAL_PAIRS (GRID_MAIN*4)

// ================= scratch =================
// g_R[(n*28+h')][idx 0..31][l 0..31]  fp16, 64B rows
__device__ __half g_R[(size_t)NB*28*32*32];   // 58.7 MB
__device__ int g_next;            // pair-level work-stealing counter
__device__ int g_done;            // reset coordinator

// ================= smem layout =================
#define WS_B32    (18*8*32*4)                   // 18432 b32 = 73728 B
#define WS_BYTES  (WS_B32*4)
#define PBUF_B32  512                           // 2KB: one chunk of 32 rows
#define NBUF      4
#define ACT_BYTES (4*NBUF*PBUF_B32*4)           // 4 pairs: 32768 B
#define GSH_OFF   (WS_BYTES + ACT_BYTES)        // 106496
#define SM_TOTAL  (GSH_OFF + 16)                // 106512

__device__ __forceinline__ void mma_f16(float4& d, const uint4& a, uint32_t b0, uint32_t b1) {
    asm volatile(
        "mma.sync.aligned.m16n8k16.row.col.f32.f16.f16.f32 "
        "{%0,%1,%2,%3}, {%4,%5,%6,%7}, {%8,%9}, {%0,%1,%2,%3};"
        : "+f"(d.x), "+f"(d.y), "+f"(d.z), "+f"(d.w)
        : "r"(a.x), "r"(a.y), "r"(a.z), "r"(a.w), "r"(b0), "r"(b1));
}

// pair-local named barrier: warps {2p, 2p+1}, 64 threads, id p+1
#define PAIRBAR(p) asm volatile("bar.sync %0, 64;" :: "r"((p) + 1) : "memory")

// ================= prep kernel (unchanged, validated R9/R10) =================
__global__ __launch_bounds__(128) void prep_kernel(const float* __restrict__ x) {
    __shared__ float xs[64 * 29];
    const int p = blockIdx.x;            // n*28 + h'
    const int n = p / 28, h = p - n * 28;
    const int tid = threadIdx.x;

    const float4* x4 = reinterpret_cast<const float4*>(x);
    #pragma unroll 4
    for (int e = tid; e < 448; e += 128) {
        const int c = e / 7, f = e - c * 7;
        const float4 v = x4[((size_t)(n * 64 + c) * 28 + h) * 7 + f];
        float* dst = &xs[c * 29 + f * 4];
        dst[0] = v.x; dst[1] = v.y; dst[2] = v.z; dst[3] = v.w;
    }
    __syncthreads();

    __half* Rout = g_R + (size_t)p * 1024;
    const int l = tid & 31;
    const int q0 = tid >> 5;
    #pragma unroll
    for (int qq = 0; qq < 8; ++qq) {
        const int q = qq * 4 + q0;
        float v;
        if (q < 28) {
            int u1 = q - 1; if (u1 < 0) u1 += 28;
            int u2 = q - 2; if (u2 < 0) u2 += 28;
            v = xs[l * 29 + u1] + xs[(32 + l) * 29 + u2];
        } else if (q == 28) v = xs[(32 + l) * 29 + 25];   // k=0, w=0
        else if (q == 29)   v = xs[l * 29 + 27];          // k=0, w=1
        else if (q == 30)   v = xs[l * 29 + 0];           // k=2, w=0
        else                v = xs[(32 + l) * 29 + 26];   // k=2, w=27
        Rout[q * 32 + l] = __float2half_rn(v);
    }
}

// ================= main kernel =================
__global__ __launch_bounds__(THREADS, 2) void main_kernel(const float* __restrict__ Wg,
                                                          float* __restrict__ out) {
    extern __shared__ char smem[];
    uint32_t* wsb = reinterpret_cast<uint32_t*>(smem);
    const uint4* ws4 = reinterpret_cast<const uint4*>(smem);
    int* gsh = reinterpret_cast<int*>(smem + GSH_OFF);

    const int tid  = threadIdx.x;
    const int lane = tid & 31;
    const int w    = tid >> 5;
    const int warp_i = w & 1;       // 64i half
    const int pair   = w >> 1;      // pair id (0..3)
    const int gq  = lane >> 2;      // fragment groupID
    const int tig = lane & 3;       // thread-in-group

    // pair-private act region: 4 buffers x 512 b32
    uint32_t* pact = reinterpret_cast<uint32_t*>(smem + WS_BYTES) + pair * (NBUF * PBUF_B32);

    // ---- weights -> fp16 fragment-ready smem, once per CTA (validated R9/R10) ----
    for (int t = tid; t < WS_B32; t += THREADS) {
        const int reg = t & 3;
        const int ln  = (t >> 2) & 31;
        const int mt  = (t >> 7) & 7;
        const int S   = t >> 10;                  // 0..17
        const int r   = (ln >> 2) + ((reg & 1) << 3);
        const int k16 = ((ln & 3) << 1) + ((reg >> 1) << 3);
        const int i   = (mt << 4) + r;
        const int kp  = (S << 4) + k16;           // even
        const int c   = kp >> 5, l = kp & 31;
        const float w0 = Wg[(l * 9 + c) * 128 + i];
        const float w1 = Wg[((l + 1) * 9 + c) * 128 + i];
        const __half2 hv = __floats2half2_rn(w0, w1);
        wsb[t] = *reinterpret_cast<const uint32_t*>(&hv);
    }
    __syncthreads();   // the only CTA-wide barrier

    // rr-dependent swizzled lane offsets for B-frag loads (R10 swizzle, pair-local)
    int lofs[4];
    #pragma unroll
    for (int rr = 0; rr < 4; ++rr)
        lofs[rr] = ((gq ^ (rr << 1)) << 2) + tig;

    // ---- staging identity: 2 rows of 8 within the pair's 32m, one 16B slot each ----
    const int srow = lane >> 2;     // 0..7
    const int slot = lane & 3;      // rr
    int dstb[2];
    #pragma unroll
    for (int q = 0; q < 2; ++q) {
        const int m_loc = warp_i * 16 + q * 8 + srow;     // 0..31 within pair
        dstb[q] = (((slot << 2) + (m_loc >> 3)) << 5)
                + (((m_loc & 7) ^ (slot << 1)) << 2);
    }

    // ---- fully pair-independent work-stealing loop ----
    while (true) {
        if (warp_i == 0 && lane == 0) gsh[pair] = atomicAdd(&g_next, 1);
        PAIRBAR(pair);
        const int u = gsh[pair];
        if (u >= UNITS) break;
        const int mbase = u << 5;

        // per-row metadata (registers)
        int hq[2], baseq[2], ikp[2];
        #pragma unroll
        for (int q = 0; q < 2; ++q) {
            const int m_loc = warp_i * 16 + q * 8 + srow;
            const int mg = mbase + m_loc;
            const int n  = mg / 784;
            const int r  = mg - n * 784;
            const int h  = r / 28;
            const int wp = r - h * 28;
            hq[q]    = h;
            baseq[q] = (n * 28 + h) << 10;        // halves
            const int ik0 = (wp == 0) ? 28 : (wp == 1) ? 29 : (wp - 1);
            const int ik2 = (wp == 0) ? 30 : (wp == 27) ? 31 : (wp + 1);
            ikp[q] = ik0 | (wp << 5) | (ik2 << 10);
        }

        uint4 sv[2];
        #define LDG_CHUNK(cn)  do {                                              \
            const int jj = ((cn) * 11) >> 5;                                     \
            const int kk = (cn) - jj * 3;                                        \
            _Pragma("unroll")                                                    \
            for (int q = 0; q < 2; ++q) {                                        \
                const int hp = hq[q] + jj - 1;                                   \
                const int ik = (ikp[q] >> (kk * 5)) & 31;                        \
                const int off = baseq[q] + ((jj - 1) << 10) + (ik << 5);         \
                sv[q] = make_uint4(0u, 0u, 0u, 0u);                              \
                if ((unsigned)hp < 28u)                                          \
                    sv[q] = *reinterpret_cast<const uint4*>(g_R + off + (slot << 3)); \
            } } while (0)
        #define STS_CHUNK(cn) do {                                               \
            uint32_t* bufn = pact + ((cn) & 3) * PBUF_B32;                       \
            _Pragma("unroll")                                                    \
            for (int q = 0; q < 2; ++q)                                          \
                *reinterpret_cast<uint4*>(bufn + dstb[q]) = sv[q];               \
            } while (0)

        // ---- prologue: stage chunks 0,1; LDG chunk 2 in flight ----
        LDG_CHUNK(0); STS_CHUNK(0);
        LDG_CHUNK(1); STS_CHUNK(1);
        LDG_CHUNK(2);
        PAIRBAR(pair);

        float4 acc[4][4];
        #pragma unroll
        for (int a = 0; a < 4; ++a)
            #pragma unroll
            for (int b = 0; b < 4; ++b)
                acc[a][b] = make_float4(0.f, 0.f, 0.f, 0.f);

        // ---- 9 chunks: STS(c+2) -> LDG(c+3) -> MMA(c) -> bar after odd c & 8 ----
        #pragma unroll 1
        for (int c = 0; c < 9; ++c) {
            if (c <= 6) STS_CHUNK(c + 2);
            if (c <= 5) LDG_CHUNK(c + 3);

            const uint32_t* bufc = pact + (c & 3) * PBUF_B32;
            #pragma unroll
            for (int s = 0; s < 2; ++s) {
                const int S = c * 2 + s;
                uint4 afr[4];
                #pragma unroll
                for (int mtl = 0; mtl < 4; ++mtl)
                    afr[mtl] = ws4[((S << 3) + warp_i * 4 + mtl) * 32 + lane];
                const int rr0 = s * 2, rr1 = s * 2 + 1;
                uint2 bfr[4];
                #pragma unroll
                for (int ntl = 0; ntl < 4; ++ntl) {
                    bfr[ntl].x = bufc[(((rr0 << 2) + ntl) << 5) + lofs[rr0]];
                    bfr[ntl].y = bufc[(((rr1 << 2) + ntl) << 5) + lofs[rr1]];
                }
                #pragma unroll
                for (int mtl = 0; mtl < 4; ++mtl)
                    #pragma unroll
                    for (int ntl = 0; ntl < 4; ++ntl)
                        mma_f16(acc[mtl][ntl], afr[mtl], bfr[ntl].x, bfr[ntl].y);
            }

            if ((c & 1) || c == 8) PAIRBAR(pair);
        }

        // ---- epilogue: coalesced float2 stores ----
        #pragma unroll
        for (int mtl = 0; mtl < 4; ++mtl) {
            const int i0 = warp_i * 64 + mtl * 16 + gq;
            #pragma unroll
            for (int ntl = 0; ntl < 4; ++ntl) {
                const int mgo = mbase + ntl * 8 + (tig << 1);
                const int n = mgo / 784;
                const int r = mgo - n * 784;     // float2 never straddles n (mgo even)
                const float4 v = acc[mtl][ntl];
                float* ob = out + (size_t)n * (IIC * 784) + r;
                *reinterpret_cast<float2*>(ob + (size_t)i0 * 784)       = make_float2(v.x, v.y);
                *reinterpret_cast<float2*>(ob + (size_t)(i0 + 8) * 784) = make_float2(v.z, v.w);
            }
        }
        // next unit's STS(0)->buf0 safe: MMA(8,buf0) of both warps done at c=8 bar,
        // and the fetch PAIRBAR adds another ordering point.
        #undef LDG_CHUNK
        #undef STS_CHUNK
    }

    // ---- self-reset of work counters (deterministic, graph-replay safe) ----
    if (warp_i == 0 && lane == 0) {
        const int old = atomicAdd(&g_done, 1);
        if (old == TOTAL_PAIRS - 1) {   // every pair has finished
            g_next = 0;
            __threadfence();
            g_done = 0;
        }
    }
}

// ================= launch =================
extern "C" void kernel_launch(void* const* d_in, const int* in_sizes, int n_in,
                              void* d_out, int out_size) {
    const float* x  = (const float*)d_in[0];   // (1024,64,28,28)
    const float* Wg = (const float*)d_in[1];   // (32,3,3,128)
    float* out = (float*)d_out;                // (1024,128,28,28)

    prep_kernel<<<NB * 28, 128>>>(x);

    cudaFuncSetAttribute(main_kernel, cudaFuncAttributeMaxDynamicSharedMemorySize, SM_TOTAL);
    main_kernel<<<GRID_MAIN, THREADS, SM_TOTAL>>>(Wg, out);
}